// round 9
// baseline (speedup 1.0000x reference)
#include <cuda_runtime.h>

#define BB 2
#define KK 4
#define DD 128
#define HH 128
#define WW 128
#define NN (DD*HH*WW)          // 2097152
#define TY 8
#define TZ 16
#define NBLK ((DD/TZ)*(HH/TY)*BB)   // 8*16*2 = 256 blocks
#define REG_WT 0.0008

// dynamic smem layout
#define SM_RAW  (3*KK*(TY+2)*32*16)    // 61440  (3 plane buffers of p, f32x4)
#define SM_IMG  (3*TY*32*16)           // 12288  (3 img plane buffers)
#define SM_RED  (16*8*4)               // 512    (block-reduce scratch, 13 used)
#define SM_FIN  (32*8)                 // 256    (final combine, 25 doubles used)
#define SMEM_TOTAL (SM_RAW + SM_IMG + SM_RED + SM_FIN)   // 74496

// ---------------- global scratch (no allocs allowed) ----------------
__device__ double   g_part[NBLK][16];  // per-block partials: A[4],B[4],C[4],J2
__device__ unsigned g_ticket;          // zero-init at load; last block resets to 0

__device__ __forceinline__ float warp_red(float v) {
    #pragma unroll
    for (int o = 16; o > 0; o >>= 1) v += __shfl_down_sync(0xffffffffu, v, o);
    return v;
}

// Single fused kernel: 2-deep cp.async pipelined 3D stencil + all reductions.
// block = (32, 8): warp w owns y-row y0+w (full x = 32 lanes x float4).
__global__ __launch_bounds__(256, 2) void rfcm_kernel(const float* __restrict__ yp,
                                                      const float* __restrict__ img,
                                                      float* __restrict__ out) {
    extern __shared__ char dsm[];
    float4 (*raw)[KK][TY+2][32] = (float4 (*)[KK][TY+2][32])(dsm);
    float4 (*imgb)[TY][32]      = (float4 (*)[TY][32])(dsm + SM_RAW);
    float  (*red)[8]            = (float (*)[8])(dsm + SM_RAW + SM_IMG);
    double *fin                 = (double*)(dsm + SM_RAW + SM_IMG + SM_RED);
    __shared__ unsigned s_last;

    const int lane = threadIdx.x;          // 0..31 -> x quad [4*lane, 4*lane+3]
    const int w    = threadIdx.y;          // 0..7 warp id == y row in tile
    const int zc = blockIdx.x;             // 0..7
    const int yt = blockIdx.y;             // 0..15
    const int b  = blockIdx.z;             // 0..1
    const int y0 = yt * TY;
    const int z0 = zc * TZ;
    const int bid = zc + (DD/TZ)*yt + (DD/TZ)*(HH/TY)*b;
    const float* __restrict__ imb = img + (size_t)b * NN;

    // issue cp.async group for plane pz: 40 yp rows + 8 img rows (plane pz-1)
    auto issue_plane = [&](int pz) {
        const int buf = (pz - z0 + 1) % 3;         // pz >= z0-1 -> >= 0
        const bool zok = (pz >= 0) && (pz < DD);
        #pragma unroll
        for (int i = 0; i < 6; i++) {
            int r = w + 8*i;                       // 0..47
            if (r < 40) {                          // yp rows (compile-time: i<5)
                int c  = r / 10;
                int yy = r - 10*c;
                int gyy = y0 + yy - 1;
                bool ok = zok && (gyy >= 0) && (gyy < HH);
                const float* src = yp + ((size_t)(b*KK + c))*NN
                                      + (size_t)(ok ? pz : 0)*(HH*WW)
                                      + (size_t)(ok ? gyy : 0)*WW + 4*lane;
                unsigned dst = (unsigned)__cvta_generic_to_shared(&raw[buf][c][yy][lane]);
                int sz = ok ? 16 : 0;              // src-size 0 -> zero-fill
                asm volatile("cp.async.cg.shared.global [%0], [%1], 16, %2;\n"
                             :: "r"(dst), "l"(src), "r"(sz));
            } else {                               // img row for plane pz-1 (i==5)
                int yy = r - 40;
                int pzi = pz - 1;
                bool ok = (pzi >= z0) && (pzi < z0 + TZ);
                const float* src = imb + (size_t)(ok ? pzi : 0)*(HH*WW)
                                       + (size_t)(y0 + yy)*WW + 4*lane;
                unsigned dst = (unsigned)__cvta_generic_to_shared(&imgb[buf][yy][lane]);
                int sz = ok ? 16 : 0;
                asm volatile("cp.async.cg.shared.global [%0], [%1], 16, %2;\n"
                             :: "r"(dst), "l"(src), "r"(sz));
            }
        }
        asm volatile("cp.async.commit_group;\n");
    };

    // z-ring registers (per channel, float4 lanes):
    // sA = s_{pz-1}, sB = s_{pz-2}+s_{pz-1}, mP = center mem of plane pz-1
    float4 sA[KK], sB[KK], mP[KK];
    #pragma unroll
    for (int c = 0; c < KK; c++) {
        sA[c] = make_float4(0,0,0,0);
        sB[c] = make_float4(0,0,0,0);
        mP[c] = make_float4(0,0,0,0);
    }
    float4 aJ2 = make_float4(0,0,0,0);
    float Acc[KK] = {0,0,0,0};     // sum mem*img^2
    float Bcc[KK] = {0,0,0,0};     // sum mem*img
    float Ccc[KK] = {0,0,0,0};     // sum mem

    issue_plane(z0 - 1);
    issue_plane(z0);

    for (int pz = z0 - 1; pz <= z0 + TZ; ++pz) {
        const int buf = (pz - z0 + 1) % 3;

        asm volatile("cp.async.wait_group 1;\n" ::: "memory");  // plane pz done; pz+1 flying
        __syncthreads();
        if (pz + 2 <= z0 + TZ) issue_plane(pz + 2);             // 2-deep during compute

        const bool emit = (pz > z0);
        float4 iv = make_float4(0,0,0,0);
        if (emit) iv = imgb[buf][w][lane];      // img plane pz-1 (arrived with group pz)
        float4 ivsq;
        ivsq.x = iv.x*iv.x; ivsq.y = iv.y*iv.y; ivsq.z = iv.z*iv.z; ivsq.w = iv.w*iv.w;

        float4 Ms = make_float4(0,0,0,0), Tnb = make_float4(0,0,0,0);
        float4 dmn = make_float4(0,0,0,0);

        #pragma unroll
        for (int c = 0; c < KK; c++) {
            // vertical 3-tap from smem (square on read: mem = p^2)
            float4 r0 = raw[buf][c][w  ][lane];
            float4 r1 = raw[buf][c][w+1][lane];
            float4 r2 = raw[buf][c][w+2][lane];
            r0.x *= r0.x; r0.y *= r0.y; r0.z *= r0.z; r0.w *= r0.w;
            r1.x *= r1.x; r1.y *= r1.y; r1.z *= r1.z; r1.w *= r1.w;
            r2.x *= r2.x; r2.y *= r2.y; r2.z *= r2.z; r2.w *= r2.w;
            float4 ry;
            ry.x = r0.x + r1.x + r2.x;
            ry.y = r0.y + r1.y + r2.y;
            ry.z = r0.z + r1.z + r2.z;
            ry.w = r0.w + r1.w + r2.w;
            // horizontal 3-tap via shuffles (warp spans full x-row)
            float lf = __shfl_up_sync  (0xffffffffu, ry.w, 1);
            float rt = __shfl_down_sync(0xffffffffu, ry.x, 1);
            lf = (lane == 0)  ? 0.f : lf;
            rt = (lane == 31) ? 0.f : rt;
            float4 s;                       // 2D 3x3 sum at plane pz
            s.x = lf   + ry.x + ry.y;
            s.y = ry.x + ry.y + ry.z;
            s.z = ry.y + ry.z + ry.w;
            s.w = ry.z + ry.w + rt;

            if (emit) {
                float4 m = mP[c];           // mem at plane pz-1 center
                float4 box, nb;
                box.x = sB[c].x + s.x;  box.y = sB[c].y + s.y;
                box.z = sB[c].z + s.z;  box.w = sB[c].w + s.w;
                nb.x = box.x - m.x; nb.y = box.y - m.y;
                nb.z = box.z - m.z; nb.w = box.w - m.w;
                Ms.x += m.x; Ms.y += m.y; Ms.z += m.z; Ms.w += m.w;
                Tnb.x += nb.x; Tnb.y += nb.y; Tnb.z += nb.z; Tnb.w += nb.w;
                dmn.x += m.x*nb.x; dmn.y += m.y*nb.y;
                dmn.z += m.z*nb.z; dmn.w += m.w*nb.w;
                // J1 scalar moments
                Ccc[c] += (m.x + m.y) + (m.z + m.w);
                Bcc[c] += m.x*iv.x  + m.y*iv.y  + m.z*iv.z  + m.w*iv.w;
                Acc[c] += m.x*ivsq.x + m.y*ivsq.y + m.z*ivsq.z + m.w*ivsq.w;
            }
            // ring update
            sB[c].x = sA[c].x + s.x; sB[c].y = sA[c].y + s.y;
            sB[c].z = sA[c].z + s.z; sB[c].w = sA[c].w + s.w;
            sA[c] = s;
            mP[c] = r1;
        }
        if (emit) {
            aJ2.x += Tnb.x*Ms.x - dmn.x;
            aJ2.y += Tnb.y*Ms.y - dmn.y;
            aJ2.z += Tnb.z*Ms.z - dmn.z;
            aJ2.w += Tnb.w*Ms.w - dmn.w;
        }
    }

    // ---- block reduce 13 scalars -> g_part[bid] ----
    float vals[13];
    #pragma unroll
    for (int c = 0; c < KK; c++) { vals[c] = Acc[c]; vals[4+c] = Bcc[c]; vals[8+c] = Ccc[c]; }
    vals[12] = (aJ2.x + aJ2.y) + (aJ2.z + aJ2.w);
    #pragma unroll
    for (int j = 0; j < 13; j++) {
        float v = warp_red(vals[j]);
        if (lane == 0) red[j][w] = v;
    }
    __syncthreads();
    if (w == 0) {
        #pragma unroll
        for (int j = 0; j < 13; j++) {
            float v = (lane < 8) ? red[j][lane] : 0.f;
            v = warp_red(v);
            if (lane == 0) g_part[bid][j] = (double)v;
        }
    }
    __threadfence();
    __syncthreads();
    const int tid = w*32 + lane;
    if (tid == 0) s_last = (atomicAdd(&g_ticket, 1u) == NBLK - 1) ? 1u : 0u;
    __syncthreads();

    if (s_last) {
        __threadfence();            // acquire: other blocks' g_part now visible
        if (tid < 25) fin[tid] = 0.0;
        __syncthreads();
        if (tid < NBLK) {           // 256 threads, one per block's partials
            int bb = tid >> 7;      // batch of that block
            #pragma unroll
            for (int c = 0; c < KK; c++) {
                atomicAdd(&fin[bb*KK + c],      g_part[tid][c]);      // A
                atomicAdd(&fin[8 + bb*KK + c],  g_part[tid][4 + c]);  // B
                atomicAdd(&fin[16 + bb*KK + c], g_part[tid][8 + c]);  // C
            }
            atomicAdd(&fin[24], g_part[tid][12]);                     // J2
        }
        __syncthreads();
        if (tid == 0) {
            double J1 = 0.0;
            #pragma unroll
            for (int ch = 0; ch < BB*KK; ch++)
                J1 += fin[ch] - fin[8+ch]*fin[8+ch] / fin[16+ch];
            double denom = (double)BB * (double)NN;
            out[0] = (float)((J1 + REG_WT * fin[24]) / denom);
            g_ticket = 0u;          // self-reset for next launch
        }
    }
}

extern "C" void kernel_launch(void* const* d_in, const int* in_sizes, int n_in,
                              void* d_out, int out_size) {
    const float* yp  = (const float*)d_in[0];   // y_pred [2,4,128,128,128]
    const float* img = (const float*)d_in[1];   // image  [2,1,128,128,128]
    (void)in_sizes; (void)n_in; (void)out_size;

    cudaFuncSetAttribute(rfcm_kernel, cudaFuncAttributeMaxDynamicSharedMemorySize,
                         SMEM_TOTAL);
    rfcm_kernel<<<dim3(DD/TZ, HH/TY, BB), dim3(32, TY), SMEM_TOTAL>>>(
        yp, img, (float*)d_out);
}

// round 10
// speedup vs baseline: 1.1108x; 1.1108x over previous
#include <cuda_runtime.h>

#define BB 2
#define KK 4
#define DD 128
#define HH 128
#define WW 128
#define NN (DD*HH*WW)          // 2097152
#define TY 8
#define TZ 16
#define NBLK ((DD/TZ)*(HH/TY)*BB)   // 8*16*2 = 256 blocks
#define REG_WT 0.0008

// dynamic smem layout
#define SM_RAW  (2*KK*(TY+2)*32*16)    // 40960  (2 plane buffers of p, f32x4)
#define SM_IMG  (2*TY*32*16)           // 8192   (2 img plane buffers)
#define SM_RED  (512)                  // block-reduce scratch (10x8 floats used)
#define SM_FIN  (256)                  // final combine (18 doubles used)
#define SMEM_TOTAL (SM_RAW + SM_IMG + SM_RED + SM_FIN)   // 49920

// ---------------- global scratch (no allocs allowed) ----------------
__device__ double   g_part[NBLK][10];  // per-block partials: B[4],C[4],A,J2
__device__ unsigned g_ticket;          // zero-init at load; last block resets to 0

__device__ __forceinline__ float warp_red(float v) {
    #pragma unroll
    for (int o = 16; o > 0; o >>= 1) v += __shfl_down_sync(0xffffffffu, v, o);
    return v;
}

// Single fused kernel: double-buffered cp.async stencil + all reductions.
// block = (32, 8): warp w owns y-row y0+w (full x = 32 lanes x float4).
__global__ __launch_bounds__(256, 2) void rfcm_kernel(const float* __restrict__ yp,
                                                      const float* __restrict__ img,
                                                      float* __restrict__ out) {
    extern __shared__ char dsm[];
    float4 (*raw)[KK][TY+2][32] = (float4 (*)[KK][TY+2][32])(dsm);
    float4 (*imgb)[TY][32]      = (float4 (*)[TY][32])(dsm + SM_RAW);
    float  (*red)[8]            = (float (*)[8])(dsm + SM_RAW + SM_IMG);
    double *fin                 = (double*)(dsm + SM_RAW + SM_IMG + SM_RED);
    __shared__ unsigned s_last;

    const int lane = threadIdx.x;          // 0..31 -> x quad [4*lane, 4*lane+3]
    const int w    = threadIdx.y;          // 0..7 warp id == y row in tile
    const int zc = blockIdx.x;             // 0..7
    const int yt = blockIdx.y;             // 0..15
    const int b  = blockIdx.z;             // 0..1
    const int y0 = yt * TY;
    const int z0 = zc * TZ;
    const int bid = zc + (DD/TZ)*yt + (DD/TZ)*(HH/TY)*b;
    const float* __restrict__ imb = img + (size_t)b * NN;

    // issue cp.async group for plane pz: 40 yp rows + 8 img rows (plane pz-1)
    auto issue_plane = [&](int pz) {
        const int buf = pz & 1;
        const bool zok = (pz >= 0) && (pz < DD);
        #pragma unroll
        for (int i = 0; i < 6; i++) {
            int r = w + 8*i;                       // 0..47
            if (r < 40) {                          // yp rows (compile-time: i<5)
                int c  = r / 10;
                int yy = r - 10*c;
                int gyy = y0 + yy - 1;
                bool ok = zok && (gyy >= 0) && (gyy < HH);
                const float* src = yp + ((size_t)(b*KK + c))*NN
                                      + (size_t)(ok ? pz : 0)*(HH*WW)
                                      + (size_t)(ok ? gyy : 0)*WW + 4*lane;
                unsigned dst = (unsigned)__cvta_generic_to_shared(&raw[buf][c][yy][lane]);
                int sz = ok ? 16 : 0;              // src-size 0 -> zero-fill
                asm volatile("cp.async.cg.shared.global [%0], [%1], 16, %2;\n"
                             :: "r"(dst), "l"(src), "r"(sz));
            } else {                               // img row for plane pz-1 (i==5)
                int yy = r - 40;
                int pzi = pz - 1;
                bool ok = (pzi >= z0) && (pzi < z0 + TZ);
                const float* src = imb + (size_t)(ok ? pzi : 0)*(HH*WW)
                                       + (size_t)(y0 + yy)*WW + 4*lane;
                unsigned dst = (unsigned)__cvta_generic_to_shared(&imgb[buf][yy][lane]);
                int sz = ok ? 16 : 0;
                asm volatile("cp.async.cg.shared.global [%0], [%1], 16, %2;\n"
                             :: "r"(dst), "l"(src), "r"(sz));
            }
        }
        asm volatile("cp.async.commit_group;\n");
    };

    // z-ring registers (per channel, float4 lanes):
    // sA = s_{pz-1}, sB = s_{pz-2}+s_{pz-1}, mP = center mem of plane pz-1
    float4 sA[KK], sB[KK], mP[KK];
    #pragma unroll
    for (int c = 0; c < KK; c++) {
        sA[c] = make_float4(0,0,0,0);
        sB[c] = make_float4(0,0,0,0);
        mP[c] = make_float4(0,0,0,0);
    }
    float Atot = 0.f, aJ2 = 0.f;       // sum mem_tot*img^2 ; J2 partial
    float Bcc[KK] = {0,0,0,0};         // sum mem*img  (per channel)
    float Ccc[KK] = {0,0,0,0};         // sum mem      (per channel)

    issue_plane(z0 - 1);

    for (int pz = z0 - 1; pz <= z0 + TZ; ++pz) {
        const int buf = pz & 1;

        asm volatile("cp.async.wait_group 0;\n" ::: "memory");  // plane pz resident
        __syncthreads();
        if (pz < z0 + TZ) issue_plane(pz + 1);  // next plane flies during compute

        const bool emit = (pz > z0);
        float4 iv = make_float4(0,0,0,0);
        if (emit) iv = imgb[buf][w][lane];      // img plane pz-1 (arrived with group pz)
        float4 ivsq;
        ivsq.x = iv.x*iv.x; ivsq.y = iv.y*iv.y; ivsq.z = iv.z*iv.z; ivsq.w = iv.w*iv.w;

        float4 Ms = make_float4(0,0,0,0), Tnb = make_float4(0,0,0,0);
        float4 dmn = make_float4(0,0,0,0);

        #pragma unroll
        for (int c = 0; c < KK; c++) {
            // vertical 3-tap from smem (square on read: mem = p^2)
            float4 r0 = raw[buf][c][w  ][lane];
            float4 r1 = raw[buf][c][w+1][lane];
            float4 r2 = raw[buf][c][w+2][lane];
            r0.x *= r0.x; r0.y *= r0.y; r0.z *= r0.z; r0.w *= r0.w;
            r1.x *= r1.x; r1.y *= r1.y; r1.z *= r1.z; r1.w *= r1.w;
            r2.x *= r2.x; r2.y *= r2.y; r2.z *= r2.z; r2.w *= r2.w;
            float4 ry;
            ry.x = r0.x + r1.x + r2.x;
            ry.y = r0.y + r1.y + r2.y;
            ry.z = r0.z + r1.z + r2.z;
            ry.w = r0.w + r1.w + r2.w;
            // horizontal 3-tap via shuffles (warp spans full x-row)
            float lf = __shfl_up_sync  (0xffffffffu, ry.w, 1);
            float rt = __shfl_down_sync(0xffffffffu, ry.x, 1);
            lf = (lane == 0)  ? 0.f : lf;
            rt = (lane == 31) ? 0.f : rt;
            float4 s;                       // 2D 3x3 sum at plane pz
            s.x = lf   + ry.x + ry.y;
            s.y = ry.x + ry.y + ry.z;
            s.z = ry.y + ry.z + ry.w;
            s.w = ry.z + ry.w + rt;

            if (emit) {
                float4 m = mP[c];           // mem at plane pz-1 center
                float4 box, nb;
                box.x = sB[c].x + s.x;  box.y = sB[c].y + s.y;
                box.z = sB[c].z + s.z;  box.w = sB[c].w + s.w;
                nb.x = box.x - m.x; nb.y = box.y - m.y;
                nb.z = box.z - m.z; nb.w = box.w - m.w;
                Ms.x += m.x; Ms.y += m.y; Ms.z += m.z; Ms.w += m.w;
                Tnb.x += nb.x; Tnb.y += nb.y; Tnb.z += nb.z; Tnb.w += nb.w;
                dmn.x += m.x*nb.x; dmn.y += m.y*nb.y;
                dmn.z += m.z*nb.z; dmn.w += m.w*nb.w;
                Ccc[c] += (m.x + m.y) + (m.z + m.w);
                Bcc[c] += m.x*iv.x + m.y*iv.y + m.z*iv.z + m.w*iv.w;
            }
            // ring update
            sB[c].x = sA[c].x + s.x; sB[c].y = sA[c].y + s.y;
            sB[c].z = sA[c].z + s.z; sB[c].w = sA[c].w + s.w;
            sA[c] = s;
            mP[c] = r1;
        }
        if (emit) {
            // A-moment via total membership: sum_ch mem*img^2 = Ms . ivsq
            Atot += Ms.x*ivsq.x + Ms.y*ivsq.y + Ms.z*ivsq.z + Ms.w*ivsq.w;
            aJ2  += (Tnb.x*Ms.x - dmn.x) + (Tnb.y*Ms.y - dmn.y)
                  + (Tnb.z*Ms.z - dmn.z) + (Tnb.w*Ms.w - dmn.w);
        }
    }

    // ---- block reduce 10 scalars -> g_part[bid] ----
    float vals[10];
    #pragma unroll
    for (int c = 0; c < KK; c++) { vals[c] = Bcc[c]; vals[4+c] = Ccc[c]; }
    vals[8] = Atot; vals[9] = aJ2;
    #pragma unroll
    for (int j = 0; j < 10; j++) {
        float v = warp_red(vals[j]);
        if (lane == 0) red[j][w] = v;
    }
    __syncthreads();
    if (w == 0) {
        #pragma unroll
        for (int j = 0; j < 10; j++) {
            float v = (lane < 8) ? red[j][lane] : 0.f;
            v = warp_red(v);
            if (lane == 0) g_part[bid][j] = (double)v;
        }
    }
    __threadfence();
    __syncthreads();
    const int tid = w*32 + lane;
    if (tid == 0) s_last = (atomicAdd(&g_ticket, 1u) == NBLK - 1) ? 1u : 0u;
    __syncthreads();

    if (s_last) {
        __threadfence();            // acquire: other blocks' g_part now visible
        if (tid < 18) fin[tid] = 0.0;   // fin: B[8], C[8], A, J2
        __syncthreads();
        if (tid < NBLK) {           // 256 threads, one per block's partials
            int bb = tid >> 7;      // batch of that block
            #pragma unroll
            for (int c = 0; c < KK; c++) {
                atomicAdd(&fin[bb*KK + c],     g_part[tid][c]);      // B
                atomicAdd(&fin[8 + bb*KK + c], g_part[tid][4 + c]);  // C
            }
            atomicAdd(&fin[16], g_part[tid][8]);                     // A
            atomicAdd(&fin[17], g_part[tid][9]);                     // J2
        }
        __syncthreads();
        if (tid == 0) {
            double J1 = fin[16];
            #pragma unroll
            for (int ch = 0; ch < BB*KK; ch++)
                J1 -= fin[ch]*fin[ch] / fin[8+ch];
            double denom = (double)BB * (double)NN;
            out[0] = (float)((J1 + REG_WT * fin[17]) / denom);
            g_ticket = 0u;          // self-reset for next launch
        }
    }
}

extern "C" void kernel_launch(void* const* d_in, const int* in_sizes, int n_in,
                              void* d_out, int out_size) {
    const float* yp  = (const float*)d_in[0];   // y_pred [2,4,128,128,128]
    const float* img = (const float*)d_in[1];   // image  [2,1,128,128,128]
    (void)in_sizes; (void)n_in; (void)out_size;

    cudaFuncSetAttribute(rfcm_kernel, cudaFuncAttributeMaxDynamicSharedMemorySize,
                         SMEM_TOTAL);
    rfcm_kernel<<<dim3(DD/TZ, HH/TY, BB), dim3(32, TY), SMEM_TOTAL>>>(
        yp, img, (float*)d_out);
}